// round 14
// baseline (speedup 1.0000x reference)
#include <cuda_runtime.h>

// ---------------------------------------------------------------------------
// NextVisitTime attention, 4 launches:
//   pre1 : W2 j-PAIRS (inline v), ts (m-trick), K2 (inline k).
//   preC : us[b] = upt[user[b]] @ K2.
//   att  : masked softmax for all rows -> g_att (j2-packed u64, 25MB).
//   main : 4096 blocks of 64 rows x 64 cols (col-quarter), 48KB static smem
//          -> 3 blocks/SM, 6 warps/SMSP. GEMM via FFMA2 j2-packing:
//          acc u64 = (even-j, odd-j) sums; att = uniform LDS.64 (1 wf),
//          weights = 2x LDS.128 (4 wf) -> FMA-bound at high occupancy.
// ---------------------------------------------------------------------------

#define T_SLOTS 24
#define D_MODEL 256
#define B_BATCH 512
#define N_ROWS  65536
#define J_DIM   96
#define J2      48
#define HD      64

typedef unsigned long long u64;

__device__ float g_ts [T_SLOTS * J_DIM];
__device__ float g_K2 [D_MODEL * J_DIM];             // scale folded in
__device__ float g_us [B_BATCH * J_DIM];
__device__ u64   g_W2p[J2 * D_MODEL];                // (W2[2k][c], W2[2k+1][c])
__device__ u64   g_att[(size_t)N_ROWS * J2];         // (att[2k], att[2k+1])

__device__ __forceinline__ u64 pack2(float x, float y) {
    u64 r; asm("mov.b64 %0, {%1, %2};" : "=l"(r) : "f"(x), "f"(y)); return r;
}
__device__ __forceinline__ void fma2(u64 &c, u64 a, u64 b) {
    asm("fma.rn.f32x2 %0, %1, %2, %0;" : "+l"(c) : "l"(a), "l"(b));
}
__device__ __forceinline__ float2 unpack2(u64 v) {
    float2 r; asm("mov.b64 {%0, %1}, %2;" : "=f"(r.x), "=f"(r.y) : "l"(v)); return r;
}

// ===========================================================================
// PRE1: 168 independent blocks (proven in rounds 10-12).
//   [0,48):   W2 pair row j2 (rows 2j2, 2j2+1; same head)
//   [48,72):  ts row th (m-trick over Wk)
//   [72,168): K2 col j (inline k head slice)
// ===========================================================================
__global__ __launch_bounds__(256) void pre1_kernel(
    const float* __restrict__ ts_emb,
    const float* __restrict__ Wq, const float* __restrict__ bq,
    const float* __restrict__ Wk, const float* __restrict__ bk,
    const float* __restrict__ Wv, const float* __restrict__ bv,
    const float* __restrict__ Wu)
{
    int bx = blockIdx.x, tid = threadIdx.x;

    if (bx < 48) {
        int j0 = 2 * bx;
        int h = j0 / T_SLOTS, t0 = j0 % T_SLOTS, t1 = t0 + 1;
        __shared__ __align__(16) float semb0[D_MODEL], semb1[D_MODEL];
        __shared__ __align__(16) float sv0[HD], sv1[HD];
        semb0[tid] = ts_emb[t0 * D_MODEL + tid];
        semb1[tid] = ts_emb[t1 * D_MODEL + tid];
        __syncthreads();
        float a0[4], a1[4];
        a0[0] = bv[tid]; a1[0] = a0[0];
        #pragma unroll
        for (int i = 1; i < 4; i++) { a0[i] = 0.f; a1[i] = 0.f; }
        #pragma unroll 4
        for (int c = 0; c < D_MODEL; c += 4) {
            #pragma unroll
            for (int u = 0; u < 4; u++) {
                float wv = Wv[(c + u) * D_MODEL + tid];
                a0[u] = fmaf(semb0[c + u], wv, a0[u]);
                a1[u] = fmaf(semb1[c + u], wv, a1[u]);
            }
        }
        float v0 = (a0[0] + a0[1]) + (a0[2] + a0[3]);
        float v1 = (a1[0] + a1[1]) + (a1[2] + a1[3]);
        if (tid >= h * HD && tid < h * HD + HD) {
            sv0[tid - h * HD] = v0;
            sv1[tid - h * HD] = v1;
        }
        __syncthreads();
        float b0[4], b1[4];
        #pragma unroll
        for (int i = 0; i < 4; i++) { b0[i] = 0.f; b1[i] = 0.f; }
        #pragma unroll 4
        for (int e = 0; e < HD; e += 4) {
            #pragma unroll
            for (int u = 0; u < 4; u++) {
                float wu = Wu[(h * HD + e + u) * D_MODEL + tid];
                b0[u] = fmaf(sv0[e + u], wu, b0[u]);
                b1[u] = fmaf(sv1[e + u], wu, b1[u]);
            }
        }
        float w0 = (b0[0] + b0[1]) + (b0[2] + b0[3]);
        float w1 = (b1[0] + b1[1]) + (b1[2] + b1[3]);
        g_W2p[bx * D_MODEL + tid] = pack2(w0, w1);

    } else if (bx < 72) {
        int th = bx - 48;
        __shared__ __align__(16) float semb[D_MODEL];
        __shared__ __align__(16) float stq[D_MODEL];
        __shared__ __align__(16) float smm[D_MODEL * 4];
        __shared__ float stbk[4];
        semb[tid] = ts_emb[th * D_MODEL + tid];
        __syncthreads();
        float a[8];
        a[0] = bq[tid];
        #pragma unroll
        for (int i = 1; i < 8; i++) a[i] = 0.f;
        #pragma unroll 4
        for (int c = 0; c < D_MODEL; c += 8) {
            #pragma unroll
            for (int u = 0; u < 8; u++)
                a[u] = fmaf(semb[c + u], Wq[(D_MODEL + c + u) * D_MODEL + tid], a[u]);
        }
        stq[tid] = ((a[0]+a[1])+(a[2]+a[3])) + ((a[4]+a[5])+(a[6]+a[7]));
        __syncthreads();
        {
            const float4* wr = (const float4*)(Wk + (size_t)tid * D_MODEL);
            const float4* q4 = (const float4*)stq;
            #pragma unroll
            for (int h = 0; h < 4; h++) {
                float s0 = 0.f, s1 = 0.f, s2 = 0.f, s3 = 0.f;
                #pragma unroll 4
                for (int e4 = h * 16; e4 < h * 16 + 16; e4++) {
                    float4 wv = wr[e4], qv = q4[e4];
                    s0 = fmaf(qv.x, wv.x, s0); s1 = fmaf(qv.y, wv.y, s1);
                    s2 = fmaf(qv.z, wv.z, s2); s3 = fmaf(qv.w, wv.w, s3);
                }
                smm[tid * 4 + h] = (s0 + s1) + (s2 + s3);
            }
        }
        if (tid < 4) {
            float s = 0.f;
            for (int e = 0; e < HD; e++)
                s = fmaf(stq[tid * HD + e], bk[tid * HD + e], s);
            stbk[tid] = s;
        }
        __syncthreads();
        if (tid < J_DIM) {
            int h = tid / T_SLOTS, t = tid % T_SLOTS;
            const float* er = ts_emb + t * D_MODEL;
            float s0 = 0.f, s1 = 0.f, s2 = 0.f, s3 = 0.f;
            #pragma unroll 8
            for (int c = 0; c < D_MODEL; c += 4) {
                s0 = fmaf(er[c+0], smm[(c+0)*4 + h], s0);
                s1 = fmaf(er[c+1], smm[(c+1)*4 + h], s1);
                s2 = fmaf(er[c+2], smm[(c+2)*4 + h], s2);
                s3 = fmaf(er[c+3], smm[(c+3)*4 + h], s3);
            }
            g_ts[th * J_DIM + tid] =
                (((s0 + s1) + (s2 + s3)) + stbk[h]) * 0.125f;
        }

    } else {
        int j = bx - 72;
        int h = j / T_SLOTS, t = j % T_SLOTS;
        __shared__ __align__(16) float semb[D_MODEL];
        __shared__ float part[4][HD];
        __shared__ __align__(16) float kh[HD];
        semb[tid] = ts_emb[t * D_MODEL + tid];
        __syncthreads();
        {
            int e = tid & 63, ch = tid >> 6;
            const float* wk = Wk + (size_t)(ch * 64) * D_MODEL + h * HD + e;
            float s = 0.f;
            #pragma unroll 8
            for (int cc = 0; cc < 64; cc++)
                s = fmaf(semb[ch * 64 + cc], wk[cc * D_MODEL], s);
            part[ch][e] = s;
        }
        __syncthreads();
        if (tid < HD)
            kh[tid] = ((part[0][tid] + part[1][tid]) +
                       (part[2][tid] + part[3][tid])) + bk[h * HD + tid];
        __syncthreads();
        {
            const float4* wq = (const float4*)(Wq + (size_t)tid * D_MODEL + h * HD);
            const float4* k4 = (const float4*)kh;
            float s0 = 0.f, s1 = 0.f, s2 = 0.f, s3 = 0.f;
            #pragma unroll
            for (int e4 = 0; e4 < HD / 4; e4++) {
                float4 wv = wq[e4], kv = k4[e4];
                s0 = fmaf(wv.x, kv.x, s0); s1 = fmaf(wv.y, kv.y, s1);
                s2 = fmaf(wv.z, kv.z, s2); s3 = fmaf(wv.w, kv.w, s3);
            }
            g_K2[tid * J_DIM + j] = ((s0 + s1) + (s2 + s3)) * 0.125f;
        }
    }
}

// ===========================================================================
// PREC: us[b] = upt[user[b]] @ K2  (8 users per block, 96 threads) — proven.
// ===========================================================================
__global__ __launch_bounds__(96) void preC_kernel(const int* __restrict__ user,
                                                  const float* __restrict__ upt)
{
    __shared__ float srow[8][D_MODEL];
    int b0 = blockIdx.x * 8;
    int j  = threadIdx.x;
    #pragma unroll
    for (int i = 0; i < 8; i++) {
        const float* src = upt + (size_t)__ldg(user + b0 + i) * D_MODEL;
        for (int d = j; d < D_MODEL; d += 96) srow[i][d] = src[d];
    }
    __syncthreads();
    float acc[8];
    #pragma unroll
    for (int i = 0; i < 8; i++) acc[i] = 0.0f;
    #pragma unroll 8
    for (int c = 0; c < D_MODEL; c++) {
        float w = g_K2[c * J_DIM + j];
        #pragma unroll
        for (int i = 0; i < 8; i++) acc[i] = fmaf(srow[i][c], w, acc[i]);
    }
    #pragma unroll
    for (int i = 0; i < 8; i++) g_us[(b0 + i) * J_DIM + j] = acc[i];
}

// ===========================================================================
// ATT: 512 blocks (one batch row = 128 seq rows each), 256 threads.
// Masked softmax -> j2-packed u64 att in smem -> coalesced copy to g_att.
// Dynamic smem: ts 2304 f | us 96 f | att 128*48 u64 (= 14688 floats).
// ===========================================================================
#define ASM_TS   0
#define ASM_US   2304
#define ASM_ATT  2400                                // float offset (16B-aligned)
#define ASM_F    (ASM_ATT + 128 * J2 * 2)            // 14688 floats
#define ASM_B    (ASM_F * 4)                         // 58752 bytes

__global__ __launch_bounds__(256) void att_kernel(
    const int* __restrict__ hour, const int* __restrict__ hmask)
{
    extern __shared__ float asm_[];
    float* sTs = asm_ + ASM_TS;
    float* sUs = asm_ + ASM_US;
    u64*   sA  = (u64*)(asm_ + ASM_ATT);

    int tid = threadIdx.x;
    int b   = blockIdx.x;
    int n0  = b * 128;

    {
        const float4* s2 = (const float4*)g_ts;
        float4* d2 = (float4*)sTs;
        for (int i = tid; i < (T_SLOTS * J_DIM) / 4; i += 256) d2[i] = s2[i];
        if (tid < J_DIM / 4)
            ((float4*)sUs)[tid] = ((const float4*)(g_us + b * J_DIM))[tid];
    }
    __syncthreads();

    #pragma unroll
    for (int uu = 0; uu < 2; uu++) {
        int u = tid + 256 * uu;
        int r = u >> 2, h = u & 3;
        int n = n0 + r;
        int hh = __ldg(hour + n);
        int msk[T_SLOTS];
        const int4* mp = (const int4*)(hmask + (size_t)n * T_SLOTS);
        #pragma unroll
        for (int i = 0; i < 6; i++) {
            int4 q = mp[i];
            msk[4*i] = q.x; msk[4*i+1] = q.y; msk[4*i+2] = q.z; msk[4*i+3] = q.w;
        }
        const float* usb = sUs + h * T_SLOTS;
        const float* tsb = sTs + hh * J_DIM + h * T_SLOTS;
        float sc[T_SLOTS];
        float mx = -3.0e38f;
        #pragma unroll
        for (int t = 0; t < T_SLOTS; t++) {
            sc[t] = msk[t] ? -1e9f : (usb[t] + tsb[t]);
            mx = fmaxf(mx, sc[t]);
        }
        float s = 0.0f;
        #pragma unroll
        for (int t = 0; t < T_SLOTS; t++) {
            float e = __expf(sc[t] - mx);
            sc[t] = e; s += e;
        }
        float inv = 1.0f / s;
        u64* ar = sA + r * J2 + h * 12;
        #pragma unroll
        for (int tt = 0; tt < 12; tt++)
            ar[tt] = pack2(sc[2*tt] * inv, sc[2*tt+1] * inv);
    }
    __syncthreads();

    // coalesced copy to global: 128*48 u64 = 3072 float4
    const float4* s = (const float4*)sA;
    float4* d = (float4*)(g_att + (size_t)n0 * J2);
    #pragma unroll
    for (int i = tid; i < 3072; i += 256) d[i] = s[i];
}

// ===========================================================================
// MAIN: 4096 blocks = (1024 row-blocks x 4 col-quarters), 256 threads,
// 48KB static smem -> 3 blocks/SM. Warp w -> rows [8w,8w+8); lane l
// (mod 16) -> 4 f32 cols. Per j2 per warp: 2x LDS.128 weights (4 wf) +
// 8 uniform LDS.64 att (8 wf) vs 32 FFMA2 -> FMA-bound at 6 warps/SMSP.
// ===========================================================================
__global__ __launch_bounds__(256, 3) void main_kernel(
    const float* __restrict__ bu, float* __restrict__ out)
{
    __shared__ u64 sW[J2 * 64];      // 24576 B: [j2][64 col-quarter]
    __shared__ u64 sA[64 * J2];      // 24576 B: [r][j2]

    int tid = threadIdx.x;
    int bx  = blockIdx.x;
    int rb  = bx >> 2, cq = bx & 3;
    int n0  = rb * 64;

    // load weight quarter: g_W2p row j2 has 128 f4; take f4 [cq*32, cq*32+32)
    {
        const float4* src = (const float4*)g_W2p;
        float4* dst = (float4*)sW;
        #pragma unroll
        for (int i = tid; i < J2 * 32; i += 256) {
            int j2 = i >> 5, q = i & 31;
            dst[i] = src[j2 * 128 + cq * 32 + q];
        }
    }
    // load att tile: row r has 24 f4
    {
        const float4* src = (const float4*)(g_att + (size_t)n0 * J2);
        float4* dst = (float4*)sA;
        #pragma unroll
        for (int i = tid; i < 64 * 24; i += 256)
            dst[i] = src[i];
    }
    __syncthreads();

    int w = tid >> 5, l = tid & 31;
    int lc = l & 15;                   // lanes 16-31 mirror lanes 0-15
    int r0 = w * 8;

    u64 acc[8][4];
    {
        float4 bv = __ldg((const float4*)bu + cq * 16 + lc);
        #pragma unroll
        for (int rr = 0; rr < 8; rr++) {
            acc[rr][0] = pack2(bv.x, 0.f);
            acc[rr][1] = pack2(bv.y, 0.f);
            acc[rr][2] = pack2(bv.z, 0.f);
            acc[rr][3] = pack2(bv.w, 0.f);
        }
    }
    const ulonglong2* wv = (const ulonglong2*)sW;    // 32 u128 per j2
    const u64* ap = sA + r0 * J2;
    #pragma unroll 2
    for (int j2 = 0; j2 < J2; j2++) {
        ulonglong2 w01 = wv[j2 * 32 + 2 * lc];
        ulonglong2 w23 = wv[j2 * 32 + 2 * lc + 1];
        #pragma unroll
        for (int rr = 0; rr < 8; rr++) {
            u64 a = ap[rr * J2 + j2];
            fma2(acc[rr][0], a, w01.x);
            fma2(acc[rr][1], a, w01.y);
            fma2(acc[rr][2], a, w23.x);
            fma2(acc[rr][3], a, w23.y);
        }
    }
    #pragma unroll
    for (int rr = 0; rr < 8; rr++) {
        float2 e0 = unpack2(acc[rr][0]);
        float2 e1 = unpack2(acc[rr][1]);
        float2 e2 = unpack2(acc[rr][2]);
        float2 e3 = unpack2(acc[rr][3]);
        ((float4*)out)[(size_t)(n0 + r0 + rr) * 64 + cq * 16 + lc] =
            make_float4(e0.x + e0.y, e1.x + e1.y, e2.x + e2.y, e3.x + e3.y);
    }
}

extern "C" void kernel_launch(void* const* d_in, const int* in_sizes, int n_in,
                              void* d_out, int out_size) {
    const float* ts_emb = (const float*)d_in[0];
    const int*   user   = (const int*)  d_in[1];
    const int*   hour   = (const int*)  d_in[2];
    const int*   hmask  = (const int*)  d_in[3];
    const float* upt    = (const float*)d_in[4];
    const float* Wq     = (const float*)d_in[5];
    const float* bq     = (const float*)d_in[6];
    const float* Wk     = (const float*)d_in[7];
    const float* bk     = (const float*)d_in[8];
    const float* Wv     = (const float*)d_in[9];
    const float* bv     = (const float*)d_in[10];
    const float* Wu     = (const float*)d_in[11];
    const float* bu     = (const float*)d_in[12];
    float* out = (float*)d_out;

    pre1_kernel<<<168, 256>>>(ts_emb, Wq, bq, Wk, bk, Wv, bv, Wu);
    preC_kernel<<<B_BATCH / 8, 96>>>(user, upt);

    cudaFuncSetAttribute(att_kernel, cudaFuncAttributeMaxDynamicSharedMemorySize, ASM_B);
    att_kernel<<<B_BATCH, 256, ASM_B>>>(hour, hmask);

    main_kernel<<<4096, 256>>>(bu, out);
}

// round 15
// speedup vs baseline: 3.5150x; 3.5150x over previous
#include <cuda_runtime.h>

// ---------------------------------------------------------------------------
// NextVisitTime attention — graft of the two best-measured components:
//   pre1 (216 blocks) + preC : K2-based precompute chain (~23us, benched
//        rounds 8/9/12/13, correct).
//   main : the round-3 champion GEMM (main ~91us): 256 thr, 64 rows/block,
//        thread = 4 rows x 16 interleaved f32-col-pairs, LDS.64 weights,
//        att stored as floats + pack_dup at use. DO NOT TOUCH.
// ---------------------------------------------------------------------------

#define T_SLOTS 24
#define D_MODEL 256
#define B_BATCH 512
#define N_ROWS  65536
#define J_DIM   96
#define HD      64

__device__ float g_ts[T_SLOTS * J_DIM];
__device__ float g_K2[D_MODEL * J_DIM];      // scale folded in
__device__ float g_us[B_BATCH * J_DIM];
__device__ float g_W2[J_DIM * D_MODEL];

typedef unsigned long long u64;

__device__ __forceinline__ u64 pack_dup(float x) {
    u64 r; asm("mov.b64 %0, {%1, %1};" : "=l"(r) : "f"(x)); return r;
}
__device__ __forceinline__ u64 pack2(float x, float y) {
    u64 r; asm("mov.b64 %0, {%1, %2};" : "=l"(r) : "f"(x), "f"(y)); return r;
}
__device__ __forceinline__ void fma2(u64 &c, u64 a, u64 b) {
    asm("fma.rn.f32x2 %0, %1, %2, %0;" : "+l"(c) : "l"(a), "l"(b));
}
__device__ __forceinline__ float2 unpack2(u64 v) {
    float2 r; asm("mov.b64 {%0, %1}, %2;" : "=f"(r.x), "=f"(r.y) : "l"(v)); return r;
}

// ===========================================================================
// PRE1: 216 independent blocks (verbatim from rounds 8/9 — benched correct).
//   [0,96):    W2 row j (inline v)
//   [96,120):  ts row th (inline tq, m-trick over Wk)
//   [120,216): K2 col j (inline k head slice)
// ===========================================================================
__global__ __launch_bounds__(256) void pre1_kernel(
    const float* __restrict__ ts_emb,
    const float* __restrict__ Wq, const float* __restrict__ bq,
    const float* __restrict__ Wk, const float* __restrict__ bk,
    const float* __restrict__ Wv, const float* __restrict__ bv,
    const float* __restrict__ Wu)
{
    int bx = blockIdx.x, tid = threadIdx.x;

    if (bx < 96) {
        int j = bx, h = j / T_SLOTS, t = j % T_SLOTS;
        __shared__ __align__(16) float semb[D_MODEL];
        __shared__ __align__(16) float sv[HD];
        semb[tid] = ts_emb[t * D_MODEL + tid];
        __syncthreads();
        float a[8];
        a[0] = bv[tid];
        #pragma unroll
        for (int i = 1; i < 8; i++) a[i] = 0.f;
        #pragma unroll 4
        for (int c = 0; c < D_MODEL; c += 8) {
            #pragma unroll
            for (int u = 0; u < 8; u++)
                a[u] = fmaf(semb[c + u], Wv[(c + u) * D_MODEL + tid], a[u]);
        }
        float vd = ((a[0]+a[1])+(a[2]+a[3])) + ((a[4]+a[5])+(a[6]+a[7]));
        if (tid >= h * HD && tid < h * HD + HD) sv[tid - h * HD] = vd;
        __syncthreads();
        float b[8];
        #pragma unroll
        for (int i = 0; i < 8; i++) b[i] = 0.f;
        #pragma unroll 2
        for (int e = 0; e < HD; e += 8) {
            #pragma unroll
            for (int u = 0; u < 8; u++)
                b[u] = fmaf(sv[e + u], Wu[(h * HD + e + u) * D_MODEL + tid], b[u]);
        }
        g_W2[j * D_MODEL + tid] =
            ((b[0]+b[1])+(b[2]+b[3])) + ((b[4]+b[5])+(b[6]+b[7]));

    } else if (bx < 120) {
        int th = bx - 96;
        __shared__ __align__(16) float semb[D_MODEL];
        __shared__ __align__(16) float stq[D_MODEL];
        __shared__ __align__(16) float smm[D_MODEL * 4];
        __shared__ float stbk[4];
        semb[tid] = ts_emb[th * D_MODEL + tid];
        __syncthreads();
        float a[8];
        a[0] = bq[tid];
        #pragma unroll
        for (int i = 1; i < 8; i++) a[i] = 0.f;
        #pragma unroll 4
        for (int c = 0; c < D_MODEL; c += 8) {
            #pragma unroll
            for (int u = 0; u < 8; u++)
                a[u] = fmaf(semb[c + u], Wq[(D_MODEL + c + u) * D_MODEL + tid], a[u]);
        }
        stq[tid] = ((a[0]+a[1])+(a[2]+a[3])) + ((a[4]+a[5])+(a[6]+a[7]));
        __syncthreads();
        {
            const float4* wr = (const float4*)(Wk + (size_t)tid * D_MODEL);
            const float4* q4 = (const float4*)stq;
            #pragma unroll
            for (int h = 0; h < 4; h++) {
                float s0 = 0.f, s1 = 0.f, s2 = 0.f, s3 = 0.f;
                #pragma unroll 4
                for (int e4 = h * 16; e4 < h * 16 + 16; e4++) {
                    float4 wv = wr[e4], qv = q4[e4];
                    s0 = fmaf(qv.x, wv.x, s0); s1 = fmaf(qv.y, wv.y, s1);
                    s2 = fmaf(qv.z, wv.z, s2); s3 = fmaf(qv.w, wv.w, s3);
                }
                smm[tid * 4 + h] = (s0 + s1) + (s2 + s3);
            }
        }
        if (tid < 4) {
            float s = 0.f;
            for (int e = 0; e < HD; e++)
                s = fmaf(stq[tid * HD + e], bk[tid * HD + e], s);
            stbk[tid] = s;
        }
        __syncthreads();
        if (tid < J_DIM) {
            int h = tid / T_SLOTS, t = tid % T_SLOTS;
            const float* er = ts_emb + t * D_MODEL;
            float s0 = 0.f, s1 = 0.f, s2 = 0.f, s3 = 0.f;
            #pragma unroll 8
            for (int c = 0; c < D_MODEL; c += 4) {
                s0 = fmaf(er[c+0], smm[(c+0)*4 + h], s0);
                s1 = fmaf(er[c+1], smm[(c+1)*4 + h], s1);
                s2 = fmaf(er[c+2], smm[(c+2)*4 + h], s2);
                s3 = fmaf(er[c+3], smm[(c+3)*4 + h], s3);
            }
            g_ts[th * J_DIM + tid] =
                (((s0 + s1) + (s2 + s3)) + stbk[h]) * 0.125f;
        }

    } else {
        int j = bx - 120;
        int h = j / T_SLOTS, t = j % T_SLOTS;
        __shared__ __align__(16) float semb[D_MODEL];
        __shared__ float part[4][HD];
        __shared__ __align__(16) float kh[HD];
        semb[tid] = ts_emb[t * D_MODEL + tid];
        __syncthreads();
        {
            int e = tid & 63, ch = tid >> 6;
            const float* wk = Wk + (size_t)(ch * 64) * D_MODEL + h * HD + e;
            float s = 0.f;
            #pragma unroll 8
            for (int cc = 0; cc < 64; cc++)
                s = fmaf(semb[ch * 64 + cc], wk[cc * D_MODEL], s);
            part[ch][e] = s;
        }
        __syncthreads();
        if (tid < HD)
            kh[tid] = ((part[0][tid] + part[1][tid]) +
                       (part[2][tid] + part[3][tid])) + bk[h * HD + tid];
        __syncthreads();
        {
            const float4* wq = (const float4*)(Wq + (size_t)tid * D_MODEL + h * HD);
            const float4* k4 = (const float4*)kh;
            float s0 = 0.f, s1 = 0.f, s2 = 0.f, s3 = 0.f;
            #pragma unroll
            for (int e4 = 0; e4 < HD / 4; e4++) {
                float4 wv = wq[e4], kv = k4[e4];
                s0 = fmaf(wv.x, kv.x, s0); s1 = fmaf(wv.y, kv.y, s1);
                s2 = fmaf(wv.z, kv.z, s2); s3 = fmaf(wv.w, kv.w, s3);
            }
            g_K2[tid * J_DIM + j] = ((s0 + s1) + (s2 + s3)) * 0.125f;
        }
    }
}

// ===========================================================================
// PREC: us[b] = upt[user[b]] @ K2 (verbatim from rounds 12/13 — benched).
// ===========================================================================
__global__ __launch_bounds__(96) void preC_kernel(const int* __restrict__ user,
                                                  const float* __restrict__ upt)
{
    __shared__ float srow[8][D_MODEL];
    int b0 = blockIdx.x * 8;
    int j  = threadIdx.x;            // 0..95
    #pragma unroll
    for (int i = 0; i < 8; i++) {
        const float* src = upt + (size_t)__ldg(user + b0 + i) * D_MODEL;
        for (int d = j; d < D_MODEL; d += 96) srow[i][d] = src[d];
    }
    __syncthreads();
    float acc[8];
    #pragma unroll
    for (int i = 0; i < 8; i++) acc[i] = 0.0f;
    #pragma unroll 8
    for (int c = 0; c < D_MODEL; c++) {
        float w = g_K2[c * J_DIM + j];
        #pragma unroll
        for (int i = 0; i < 8; i++) acc[i] = fmaf(srow[i][c], w, acc[i]);
    }
    #pragma unroll
    for (int i = 0; i < 8; i++) g_us[(b0 + i) * J_DIM + j] = acc[i];
}

// ===========================================================================
// MAIN: the round-3 champion (verbatim; main ~91us as part of 118.5 total).
// 256 threads, 64 rows/block. Phase 2: thread (rg,cg) = rows rg*4..+3,
// u64 weight cols {cg + 16i}; lanes 0-15 stream consecutive u64 (all banks),
// lanes 16-31 broadcast. att floats + pack_dup at use.
// SMEM (floats): W2 24576 | att 64*100 (padded) | ts 2304 | us 96
// ===========================================================================
#define SM_W2   0
#define SM_ATT  24576
#define ATT_PITCH 100
#define SM_TS   (SM_ATT + 64 * ATT_PITCH)       // 30976
#define SM_US   (SM_TS + T_SLOTS * J_DIM)       // 33280
#define SM_FLOATS (SM_US + J_DIM)               // 33376
#define SM_BYTES  (SM_FLOATS * 4)               // 133504

__global__ __launch_bounds__(256, 1) void main_kernel(
    const int* __restrict__ hour, const int* __restrict__ hmask,
    const float* __restrict__ bu, float* __restrict__ out)
{
    extern __shared__ float sm[];
    float* sW2  = sm + SM_W2;
    float* sAtt = sm + SM_ATT;
    float* sTs  = sm + SM_TS;
    float* sUs  = sm + SM_US;

    int tid = threadIdx.x;
    int n0  = blockIdx.x * 64;
    int b   = n0 >> 7;            // 64 | 128 -> whole block in one batch row

    // cooperative loads
    {
        const float4* s1 = (const float4*)g_W2;
        float4* d1 = (float4*)sW2;
        #pragma unroll
        for (int i = 0; i < 24; i++) d1[tid + i * 256] = s1[tid + i * 256];
        const float4* s2 = (const float4*)g_ts;
        float4* d2 = (float4*)sTs;
        for (int i = tid; i < (T_SLOTS * J_DIM) / 4; i += 256) d2[i] = s2[i];
        if (tid < J_DIM / 4)
            ((float4*)sUs)[tid] = ((const float4*)(g_us + b * J_DIM))[tid];
    }
    __syncthreads();

    // ---- phase 1: one thread per (row, head) masked softmax ----
    {
        int r = tid >> 2, h = tid & 3;
        int n = n0 + r;
        int hh = __ldg(hour + n);
        int msk[T_SLOTS];
        const int4* mp = (const int4*)(hmask + (size_t)n * T_SLOTS);
        #pragma unroll
        for (int i = 0; i < 6; i++) {
            int4 q = mp[i];
            msk[4*i] = q.x; msk[4*i+1] = q.y; msk[4*i+2] = q.z; msk[4*i+3] = q.w;
        }
        const float* usb = sUs + h * T_SLOTS;
        const float* tsb = sTs + hh * J_DIM + h * T_SLOTS;
        float sc[T_SLOTS];
        float mx = -3.0e38f;
        #pragma unroll
        for (int t = 0; t < T_SLOTS; t++) {
            sc[t] = msk[t] ? -1e9f : (usb[t] + tsb[t]);
            mx = fmaxf(mx, sc[t]);
        }
        float s = 0.0f;
        #pragma unroll
        for (int t = 0; t < T_SLOTS; t++) {
            float e = __expf(sc[t] - mx);
            sc[t] = e; s += e;
        }
        float inv = 1.0f / s;
        float* ar = sAtt + r * ATT_PITCH + h * T_SLOTS;
        #pragma unroll
        for (int t = 0; t < T_SLOTS; t++) ar[t] = sc[t] * inv;
    }
    __syncthreads();

    // ---- phase 2: [64 x 96] @ [96 x 256], 4 rows x 16 interleaved col-pairs
    int rg = tid >> 4, cg = tid & 15;
    int r0 = rg * 4;
    u64 acc[4][8];
    #pragma unroll
    for (int i = 0; i < 8; i++) {
        int cp = cg + i * 16;    // u64 column index (float cols 2cp, 2cp+1)
        u64 bv = pack2(__ldg(bu + 2*cp), __ldg(bu + 2*cp + 1));
        #pragma unroll
        for (int rr = 0; rr < 4; rr++) acc[rr][i] = bv;
    }
    const u64* w2p = (const u64*)sW2;
    const float* ap = sAtt + r0 * ATT_PITCH;
    #pragma unroll 2
    for (int j = 0; j < J_DIM; j++) {
        u64 w[8];
        #pragma unroll
        for (int i = 0; i < 8; i++) w[i] = w2p[j * (D_MODEL/2) + cg + i * 16];
        #pragma unroll
        for (int rr = 0; rr < 4; rr++) {
            u64 a = pack_dup(ap[rr * ATT_PITCH + j]);
            #pragma unroll
            for (int i = 0; i < 8; i++) fma2(acc[rr][i], a, w[i]);
        }
    }
    #pragma unroll
    for (int rr = 0; rr < 4; rr++) {
        float2* orow = (float2*)(out + (size_t)(n0 + r0 + rr) * D_MODEL);
        #pragma unroll
        for (int i = 0; i < 8; i++) {
            float2 v = unpack2(acc[rr][i]);
            orow[cg + i * 16] = v;
        }
    }
}

extern "C" void kernel_launch(void* const* d_in, const int* in_sizes, int n_in,
                              void* d_out, int out_size) {
    const float* ts_emb = (const float*)d_in[0];
    const int*   user   = (const int*)  d_in[1];
    const int*   hour   = (const int*)  d_in[2];
    const int*   hmask  = (const int*)  d_in[3];
    const float* upt    = (const float*)d_in[4];
    const float* Wq     = (const float*)d_in[5];
    const float* bq     = (const float*)d_in[6];
    const float* Wk     = (const float*)d_in[7];
    const float* bk     = (const float*)d_in[8];
    const float* Wv     = (const float*)d_in[9];
    const float* bv     = (const float*)d_in[10];
    const float* Wu     = (const float*)d_in[11];
    const float* bu     = (const float*)d_in[12];
    float* out = (float*)d_out;

    pre1_kernel<<<216, 256>>>(ts_emb, Wq, bq, Wk, bk, Wv, bv, Wu);
    preC_kernel<<<B_BATCH / 8, 96>>>(user, upt);

    cudaFuncSetAttribute(main_kernel, cudaFuncAttributeMaxDynamicSharedMemorySize, SM_BYTES);
    main_kernel<<<N_ROWS / 64, 256, SM_BYTES>>>(hour, hmask, bu, out);
}

// round 16
// speedup vs baseline: 4.7660x; 1.3559x over previous
#include <cuda_runtime.h>

// ---------------------------------------------------------------------------
// NextVisitTime attention — the round-3 WINNING configuration (118.5us),
// restored verbatim, with ONE change: preA's uq reduction split 2-way -> 4-way
// (g_uqA..D, 64-deep loops) to cut its latency-bound runtime further.
//   preA : k / v / tq(+bq) rows + uq quarter-partials.
//   preB : W2 rows, ts table, us = ((uqA+uqB+uqC+uqD) . k) * scale.
//   main : champion GEMM — 256 thr, 64 rows/block, 4 rows x 16 interleaved
//          f32-col-pairs, LDS.64 weights, float att + pack_dup. UNTOUCHED.
// ---------------------------------------------------------------------------

#define T_SLOTS 24
#define D_MODEL 256
#define B_BATCH 512
#define S_SEQ   128
#define N_ROWS  (B_BATCH * S_SEQ)   // 65536
#define H_HEADS 4
#define HD      64
#define J_DIM   (H_HEADS * T_SLOTS) // 96

__device__ float g_k  [T_SLOTS * D_MODEL];
__device__ float g_v  [T_SLOTS * D_MODEL];
__device__ float g_tq [T_SLOTS * D_MODEL];
__device__ float g_uqA[B_BATCH * D_MODEL];   // partial over c in [0,64)
__device__ float g_uqB[B_BATCH * D_MODEL];   // [64,128)
__device__ float g_uqC[B_BATCH * D_MODEL];   // [128,192)
__device__ float g_uqD[B_BATCH * D_MODEL];   // [192,256)
__device__ float g_ts [T_SLOTS * J_DIM];
__device__ float g_us [B_BATCH * J_DIM];
__device__ float g_W2 [J_DIM * D_MODEL];

typedef unsigned long long u64;

__device__ __forceinline__ u64 pack_dup(float x) {
    u64 r; asm("mov.b64 %0, {%1, %1};" : "=l"(r) : "f"(x)); return r;
}
__device__ __forceinline__ u64 pack2(float x, float y) {
    u64 r; asm("mov.b64 %0, {%1, %2};" : "=l"(r) : "f"(x), "f"(y)); return r;
}
__device__ __forceinline__ void fma2(u64 &c, u64 a, u64 b) {
    asm("fma.rn.f32x2 %0, %1, %2, %0;" : "+l"(c) : "l"(a), "l"(b));
}
__device__ __forceinline__ float2 unpack2(u64 v) {
    float2 r; asm("mov.b64 {%0, %1}, %2;" : "=f"(r.x), "=f"(r.y) : "l"(v)); return r;
}

// ===========================================================================
// Kernel A: layer-1 GEMMs.
//   blocks [0,72):    k / v / tq(+bq) rows (t = bx%24, z = bx/24)
//   blocks [72,328):  uq quarters: g = bx-72; users (g>>2)*8, c-quarter g&3
// ===========================================================================
__global__ __launch_bounds__(256) void preA(
    const float* __restrict__ ts_emb,
    const float* __restrict__ Wk, const float* __restrict__ bk,
    const float* __restrict__ Wv, const float* __restrict__ bv,
    const float* __restrict__ Wq, const float* __restrict__ bq,
    const int*   __restrict__ user,
    const float* __restrict__ upt)
{
    __shared__ float srow[8][D_MODEL];
    int bx = blockIdx.x;
    int d  = threadIdx.x;

    if (bx < 72) {
        int t = bx % 24, z = bx / 24;
        srow[0][d] = ts_emb[t * D_MODEL + d];
        __syncthreads();
        const float* W; const float* bias; float* outp;
        if (z == 0)      { W = Wk;                     bias = bk; outp = g_k;  }
        else if (z == 1) { W = Wv;                     bias = bv; outp = g_v;  }
        else             { W = Wq + D_MODEL * D_MODEL; bias = bq; outp = g_tq; }
        float a[8];
        a[0] = bias[d];
        #pragma unroll
        for (int i = 1; i < 8; i++) a[i] = 0.f;
        #pragma unroll 4
        for (int c = 0; c < D_MODEL; c += 8) {
            #pragma unroll
            for (int u = 0; u < 8; u++)
                a[u] = fmaf(srow[0][c + u], W[(c + u) * D_MODEL + d], a[u]);
        }
        outp[t * D_MODEL + d] =
            ((a[0] + a[1]) + (a[2] + a[3])) + ((a[4] + a[5]) + (a[6] + a[7]));
    } else {
        int g  = bx - 72;            // 0..255
        int b0 = (g >> 2) * 8;       // 8-user group
        int q  = g & 3;              // c-quarter
        int ch = q * 64;
        float* outp = (q == 0) ? g_uqA : (q == 1) ? g_uqB
                    : (q == 2) ? g_uqC : g_uqD;
        if (d < 64) {
            #pragma unroll
            for (int i = 0; i < 8; i++)
                srow[i][d] = upt[(size_t)user[b0 + i] * D_MODEL + ch + d];
        }
        __syncthreads();
        float acc[8];
        #pragma unroll
        for (int i = 0; i < 8; i++) acc[i] = 0.0f;
        #pragma unroll 8
        for (int c = 0; c < 64; c++) {
            float w = Wq[(ch + c) * D_MODEL + d];
            #pragma unroll
            for (int i = 0; i < 8; i++) acc[i] = fmaf(srow[i][c], w, acc[i]);
        }
        #pragma unroll
        for (int i = 0; i < 8; i++) outp[(b0 + i) * D_MODEL + d] = acc[i];
    }
}

// ===========================================================================
// Kernel B: second-stage precompute (verbatim R3 except 4-way uq sum).
//   blocks [0,96):    W2 row j = bx
//   blocks [96,105):  ts flat (2304 elems)
//   blocks [105,297): us flat (49152 elems)
// ===========================================================================
__global__ __launch_bounds__(256) void preB(const float* __restrict__ Wu)
{
    int bx  = blockIdx.x;
    int tid = threadIdx.x;

    if (bx < 96) {                                  // W2
        int j = bx;
        int h = j / T_SLOTS, t = j % T_SLOTS;
        __shared__ float vv[HD];
        if (tid < HD) vv[tid] = g_v[t * D_MODEL + h * HD + tid];
        __syncthreads();
        const float* W = Wu + (h * HD) * D_MODEL + tid;
        float a[8];
        #pragma unroll
        for (int i = 0; i < 8; i++) a[i] = 0.f;
        #pragma unroll 2
        for (int e = 0; e < HD; e += 8) {
            #pragma unroll
            for (int u = 0; u < 8; u++)
                a[u] = fmaf(vv[e + u], W[(e + u) * D_MODEL], a[u]);
        }
        g_W2[j * D_MODEL + tid] =
            ((a[0] + a[1]) + (a[2] + a[3])) + ((a[4] + a[5]) + (a[6] + a[7]));
    } else if (bx < 105) {                          // ts = (tq . k) * scale
        int idx = (bx - 96) * 256 + tid;
        if (idx < T_SLOTS * J_DIM) {
            int th = idx / J_DIM, jj = idx % J_DIM;
            int h = jj / T_SLOTS, t = jj % T_SLOTS;
            const float4* a4 = (const float4*)(g_tq + th * D_MODEL + h * HD);
            const float4* k4 = (const float4*)(g_k  + t  * D_MODEL + h * HD);
            float s0 = 0.f, s1 = 0.f, s2 = 0.f, s3 = 0.f;
            #pragma unroll
            for (int e = 0; e < HD / 4; e++) {
                float4 av = a4[e], kv = k4[e];
                s0 = fmaf(av.x, kv.x, s0); s1 = fmaf(av.y, kv.y, s1);
                s2 = fmaf(av.z, kv.z, s2); s3 = fmaf(av.w, kv.w, s3);
            }
            g_ts[idx] = ((s0 + s1) + (s2 + s3)) * 0.125f;
        }
    } else {                                        // us = (sum uq . k)*scale
        int idx = (bx - 105) * 256 + tid;           // < 49152 exactly
        int b = idx / J_DIM, jj = idx % J_DIM;
        int h = jj / T_SLOTS, t = jj % T_SLOTS;
        const float4* aA = (const float4*)(g_uqA + b * D_MODEL + h * HD);
        const float4* aB = (const float4*)(g_uqB + b * D_MODEL + h * HD);
        const float4* aC = (const float4*)(g_uqC + b * D_MODEL + h * HD);
        const float4* aD = (const float4*)(g_uqD + b * D_MODEL + h * HD);
        const float4* k4 = (const float4*)(g_k   + t * D_MODEL + h * HD);
        float s0 = 0.f, s1 = 0.f, s2 = 0.f, s3 = 0.f;
        #pragma unroll
        for (int e = 0; e < HD / 4; e++) {
            float4 va = aA[e], vb = aB[e], vc = aC[e], vd = aD[e], kv = k4[e];
            s0 = fmaf((va.x + vb.x) + (vc.x + vd.x), kv.x, s0);
            s1 = fmaf((va.y + vb.y) + (vc.y + vd.y), kv.y, s1);
            s2 = fmaf((va.z + vb.z) + (vc.z + vd.z), kv.z, s2);
            s3 = fmaf((va.w + vb.w) + (vc.w + vd.w), kv.w, s3);
        }
        g_us[idx] = ((s0 + s1) + (s2 + s3)) * 0.125f;
    }
}

// ===========================================================================
// MAIN: the champion (verbatim; part of the 118.5us total).
// SMEM (floats): W2 24576 | att 64*100 (padded) | ts 2304 | us 96
// ===========================================================================
#define SM_W2   0
#define SM_ATT  24576
#define ATT_PITCH 100
#define SM_TS   (SM_ATT + 64 * ATT_PITCH)       // 30976
#define SM_US   (SM_TS + T_SLOTS * J_DIM)       // 33280
#define SM_FLOATS (SM_US + J_DIM)               // 33376
#define SM_BYTES  (SM_FLOATS * 4)               // 133504

__global__ __launch_bounds__(256, 1) void main_kernel(
    const int* __restrict__ hour, const int* __restrict__ hmask,
    const float* __restrict__ bu, float* __restrict__ out)
{
    extern __shared__ float sm[];
    float* sW2  = sm + SM_W2;
    float* sAtt = sm + SM_ATT;
    float* sTs  = sm + SM_TS;
    float* sUs  = sm + SM_US;

    int tid = threadIdx.x;
    int n0  = blockIdx.x * 64;
    int b   = n0 >> 7;            // 64 | 128 -> whole block in one batch row

    // cooperative loads
    {
        const float4* s1 = (const float4*)g_W2;
        float4* d1 = (float4*)sW2;
        #pragma unroll
        for (int i = 0; i < 24; i++) d1[tid + i * 256] = s1[tid + i * 256];
        const float4* s2 = (const float4*)g_ts;
        float4* d2 = (float4*)sTs;
        for (int i = tid; i < (T_SLOTS * J_DIM) / 4; i += 256) d2[i] = s2[i];
        if (tid < J_DIM / 4)
            ((float4*)sUs)[tid] = ((const float4*)(g_us + b * J_DIM))[tid];
    }
    __syncthreads();

    // ---- phase 1: one thread per (row, head) masked softmax ----
    {
        int r = tid >> 2, h = tid & 3;
        int n = n0 + r;
        int hh = __ldg(hour + n);
        int msk[T_SLOTS];
        const int4* mp = (const int4*)(hmask + (size_t)n * T_SLOTS);
        #pragma unroll
        for (int i = 0; i < 6; i++) {
            int4 q = mp[i];
            msk[4*i] = q.x; msk[4*i+1] = q.y; msk[4*i+2] = q.z; msk[4*i+3] = q.w;
        }
        const float* usb = sUs + h * T_SLOTS;
        const float* tsb = sTs + hh * J_DIM + h * T_SLOTS;
        float sc[T_SLOTS];
        float mx = -3.0e38f;
        #pragma unroll
        for (int t = 0; t < T_SLOTS; t++) {
            sc[t] = msk[t] ? -1e9f : (usb[t] + tsb[t]);
            mx = fmaxf(mx, sc[t]);
        }
        float s = 0.0f;
        #pragma unroll
        for (int t = 0; t < T_SLOTS; t++) {
            float e = __expf(sc[t] - mx);
            sc[t] = e; s += e;
        }
        float inv = 1.0f / s;
        float* ar = sAtt + r * ATT_PITCH + h * T_SLOTS;
        #pragma unroll
        for (int t = 0; t < T_SLOTS; t++) ar[t] = sc[t] * inv;
    }
    __syncthreads();

    // ---- phase 2: [64 x 96] @ [96 x 256], 4 rows x 16 interleaved col-pairs
    int rg = tid >> 4, cg = tid & 15;
    int r0 = rg * 4;
    u64 acc[4][8];
    #pragma unroll
    for (int i = 0; i < 8; i++) {
        int cp = cg + i * 16;    // u64 column index (float cols 2cp, 2cp+1)
        u64 bv = pack2(__ldg(bu + 2*cp), __ldg(bu + 2*cp + 1));
        #pragma unroll
        for (int rr = 0; rr < 4; rr++) acc[rr][i] = bv;
    }
    const u64* w2p = (const u64*)sW2;
    const float* ap = sAtt + r0 * ATT_PITCH;
    #pragma unroll 2
    for (int j = 0; j < J_DIM; j++) {
        u64 w[8];
        #pragma unroll
        for (int i = 0; i < 8; i++) w[i] = w2p[j * (D_MODEL/2) + cg + i * 16];
        #pragma unroll
        for (int rr = 0; rr < 4; rr++) {
            u64 a = pack_dup(ap[rr * ATT_PITCH + j]);
            #pragma unroll
            for (int i = 0; i < 8; i++) fma2(acc[rr][i], a, w[i]);
        }
    }
    #pragma unroll
    for (int rr = 0; rr < 4; rr++) {
        float2* orow = (float2*)(out + (size_t)(n0 + r0 + rr) * D_MODEL);
        #pragma unroll
        for (int i = 0; i < 8; i++) {
            float2 v = unpack2(acc[rr][i]);
            orow[cg + i * 16] = v;
        }
    }
}

extern "C" void kernel_launch(void* const* d_in, const int* in_sizes, int n_in,
                              void* d_out, int out_size) {
    const float* ts_emb = (const float*)d_in[0];
    const int*   user   = (const int*)  d_in[1];
    const int*   hour   = (const int*)  d_in[2];
    const int*   hmask  = (const int*)  d_in[3];
    const float* upt    = (const float*)d_in[4];
    const float* Wq     = (const float*)d_in[5];
    const float* bq     = (const float*)d_in[6];
    const float* Wk     = (const float*)d_in[7];
    const float* bk     = (const float*)d_in[8];
    const float* Wv     = (const float*)d_in[9];
    const float* bv     = (const float*)d_in[10];
    const float* Wu     = (const float*)d_in[11];
    const float* bu     = (const float*)d_in[12];
    float* out = (float*)d_out;

    preA<<<72 + 256, 256>>>(ts_emb, Wk, bk, Wv, bv, Wq, bq, user, upt);
    preB<<<96 + 9 + 192, 256>>>(Wu);

    cudaFuncSetAttribute(main_kernel, cudaFuncAttributeMaxDynamicSharedMemorySize, SM_BYTES);
    main_kernel<<<N_ROWS / 64, 256, SM_BYTES>>>(hour, hmask, bu, out);
}

// round 17
// speedup vs baseline: 5.1655x; 1.0838x over previous
#include <cuda_runtime.h>

// ---------------------------------------------------------------------------
// NextVisitTime attention — 4 launches:
//   preA : k/v/tq rows + uq quarter-partials (R16-benched, 15.2us).
//   preB : W2 rows, ts table, us (R16-benched).
//   att  : masked softmax for all 65536 rows -> g_att floats (25MB).
//   main : PURE GEMM, col-half split: 2048 blocks of 64 rows x 128 cols,
//          ~73KB smem -> 2 blocks/SM (4 warps/SMSP). Warp = 8 rows x 128
//          cols; thread = 8 rows x 4 f32 via LDS.128 weight pair; att =
//          warp-uniform LDS.32 + pack_dup. FMA-bound with L1 slack.
// ---------------------------------------------------------------------------

#define T_SLOTS 24
#define D_MODEL 256
#define B_BATCH 512
#define S_SEQ   128
#define N_ROWS  (B_BATCH * S_SEQ)   // 65536
#define H_HEADS 4
#define HD      64
#define J_DIM   (H_HEADS * T_SLOTS) // 96

__device__ float g_k  [T_SLOTS * D_MODEL];
__device__ float g_v  [T_SLOTS * D_MODEL];
__device__ float g_tq [T_SLOTS * D_MODEL];
__device__ float g_uqA[B_BATCH * D_MODEL];
__device__ float g_uqB[B_BATCH * D_MODEL];
__device__ float g_uqC[B_BATCH * D_MODEL];
__device__ float g_uqD[B_BATCH * D_MODEL];
__device__ float g_ts [T_SLOTS * J_DIM];
__device__ float g_us [B_BATCH * J_DIM];
__device__ float g_W2 [J_DIM * D_MODEL];
__device__ float g_att[(size_t)N_ROWS * J_DIM];   // softmax weights, dense

typedef unsigned long long u64;

__device__ __forceinline__ u64 pack_dup(float x) {
    u64 r; asm("mov.b64 %0, {%1, %1};" : "=l"(r) : "f"(x)); return r;
}
__device__ __forceinline__ u64 pack2(float x, float y) {
    u64 r; asm("mov.b64 %0, {%1, %2};" : "=l"(r) : "f"(x), "f"(y)); return r;
}
__device__ __forceinline__ void fma2(u64 &c, u64 a, u64 b) {
    asm("fma.rn.f32x2 %0, %1, %2, %0;" : "+l"(c) : "l"(a), "l"(b));
}
__device__ __forceinline__ float2 unpack2(u64 v) {
    float2 r; asm("mov.b64 {%0, %1}, %2;" : "=f"(r.x), "=f"(r.y) : "l"(v)); return r;
}

// ===========================================================================
// Kernel A (verbatim R16-benched): layer-1 GEMMs.
// ===========================================================================
__global__ __launch_bounds__(256) void preA(
    const float* __restrict__ ts_emb,
    const float* __restrict__ Wk, const float* __restrict__ bk,
    const float* __restrict__ Wv, const float* __restrict__ bv,
    const float* __restrict__ Wq, const float* __restrict__ bq,
    const int*   __restrict__ user,
    const float* __restrict__ upt)
{
    __shared__ float srow[8][D_MODEL];
    int bx = blockIdx.x;
    int d  = threadIdx.x;

    if (bx < 72) {
        int t = bx % 24, z = bx / 24;
        srow[0][d] = ts_emb[t * D_MODEL + d];
        __syncthreads();
        const float* W; const float* bias; float* outp;
        if (z == 0)      { W = Wk;                     bias = bk; outp = g_k;  }
        else if (z == 1) { W = Wv;                     bias = bv; outp = g_v;  }
        else             { W = Wq + D_MODEL * D_MODEL; bias = bq; outp = g_tq; }
        float a[8];
        a[0] = bias[d];
        #pragma unroll
        for (int i = 1; i < 8; i++) a[i] = 0.f;
        #pragma unroll 4
        for (int c = 0; c < D_MODEL; c += 8) {
            #pragma unroll
            for (int u = 0; u < 8; u++)
                a[u] = fmaf(srow[0][c + u], W[(c + u) * D_MODEL + d], a[u]);
        }
        outp[t * D_MODEL + d] =
            ((a[0] + a[1]) + (a[2] + a[3])) + ((a[4] + a[5]) + (a[6] + a[7]));
    } else {
        int g  = bx - 72;            // 0..255
        int b0 = (g >> 2) * 8;
        int q  = g & 3;
        int ch = q * 64;
        float* outp = (q == 0) ? g_uqA : (q == 1) ? g_uqB
                    : (q == 2) ? g_uqC : g_uqD;
        if (d < 64) {
            #pragma unroll
            for (int i = 0; i < 8; i++)
                srow[i][d] = upt[(size_t)user[b0 + i] * D_MODEL + ch + d];
        }
        __syncthreads();
        float acc[8];
        #pragma unroll
        for (int i = 0; i < 8; i++) acc[i] = 0.0f;
        #pragma unroll 8
        for (int c = 0; c < 64; c++) {
            float w = Wq[(ch + c) * D_MODEL + d];
            #pragma unroll
            for (int i = 0; i < 8; i++) acc[i] = fmaf(srow[i][c], w, acc[i]);
        }
        #pragma unroll
        for (int i = 0; i < 8; i++) outp[(b0 + i) * D_MODEL + d] = acc[i];
    }
}

// ===========================================================================
// Kernel B (verbatim R16-benched): W2, ts, us.
// ===========================================================================
__global__ __launch_bounds__(256) void preB(const float* __restrict__ Wu)
{
    int bx  = blockIdx.x;
    int tid = threadIdx.x;

    if (bx < 96) {                                  // W2
        int j = bx;
        int h = j / T_SLOTS, t = j % T_SLOTS;
        __shared__ float vv[HD];
        if (tid < HD) vv[tid] = g_v[t * D_MODEL + h * HD + tid];
        __syncthreads();
        const float* W = Wu + (h * HD) * D_MODEL + tid;
        float a[8];
        #pragma unroll
        for (int i = 0; i < 8; i++) a[i] = 0.f;
        #pragma unroll 2
        for (int e = 0; e < HD; e += 8) {
            #pragma unroll
            for (int u = 0; u < 8; u++)
                a[u] = fmaf(vv[e + u], W[(e + u) * D_MODEL], a[u]);
        }
        g_W2[j * D_MODEL + tid] =
            ((a[0] + a[1]) + (a[2] + a[3])) + ((a[4] + a[5]) + (a[6] + a[7]));
    } else if (bx < 105) {                          // ts
        int idx = (bx - 96) * 256 + tid;
        if (idx < T_SLOTS * J_DIM) {
            int th = idx / J_DIM, jj = idx % J_DIM;
            int h = jj / T_SLOTS, t = jj % T_SLOTS;
            const float4* a4 = (const float4*)(g_tq + th * D_MODEL + h * HD);
            const float4* k4 = (const float4*)(g_k  + t  * D_MODEL + h * HD);
            float s0 = 0.f, s1 = 0.f, s2 = 0.f, s3 = 0.f;
            #pragma unroll
            for (int e = 0; e < HD / 4; e++) {
                float4 av = a4[e], kv = k4[e];
                s0 = fmaf(av.x, kv.x, s0); s1 = fmaf(av.y, kv.y, s1);
                s2 = fmaf(av.z, kv.z, s2); s3 = fmaf(av.w, kv.w, s3);
            }
            g_ts[idx] = ((s0 + s1) + (s2 + s3)) * 0.125f;
        }
    } else {                                        // us
        int idx = (bx - 105) * 256 + tid;
        int b = idx / J_DIM, jj = idx % J_DIM;
        int h = jj / T_SLOTS, t = jj % T_SLOTS;
        const float4* aA = (const float4*)(g_uqA + b * D_MODEL + h * HD);
        const float4* aB = (const float4*)(g_uqB + b * D_MODEL + h * HD);
        const float4* aC = (const float4*)(g_uqC + b * D_MODEL + h * HD);
        const float4* aD = (const float4*)(g_uqD + b * D_MODEL + h * HD);
        const float4* k4 = (const float4*)(g_k   + t * D_MODEL + h * HD);
        float s0 = 0.f, s1 = 0.f, s2 = 0.f, s3 = 0.f;
        #pragma unroll
        for (int e = 0; e < HD / 4; e++) {
            float4 va = aA[e], vb = aB[e], vc = aC[e], vd = aD[e], kv = k4[e];
            s0 = fmaf((va.x + vb.x) + (vc.x + vd.x), kv.x, s0);
            s1 = fmaf((va.y + vb.y) + (vc.y + vd.y), kv.y, s1);
            s2 = fmaf((va.z + vb.z) + (vc.z + vd.z), kv.z, s2);
            s3 = fmaf((va.w + vb.w) + (vc.w + vd.w), kv.w, s3);
        }
        g_us[idx] = ((s0 + s1) + (s2 + s3)) * 0.125f;
    }
}

// ===========================================================================
// ATT: 512 blocks (one batch row b = 128 seq rows), 256 threads.
// Masked softmax -> float att staged in smem -> coalesced float4 store.
// Dyn smem floats: ts 2304 | us 96 | att 128*96 = 14688 f (58752 B).
// ===========================================================================
#define ASM_TS   0
#define ASM_US   2304
#define ASM_ATT  2400
#define ASM_F    (ASM_ATT + 128 * J_DIM)
#define ASM_B    (ASM_F * 4)

__global__ __launch_bounds__(256) void att_kernel(
    const int* __restrict__ hour, const int* __restrict__ hmask)
{
    extern __shared__ float asm_[];
    float* sTs = asm_ + ASM_TS;
    float* sUs = asm_ + ASM_US;
    float* sA  = asm_ + ASM_ATT;

    int tid = threadIdx.x;
    int b   = blockIdx.x;
    int n0  = b * 128;

    {
        const float4* s2 = (const float4*)g_ts;
        float4* d2 = (float4*)sTs;
        for (int i = tid; i < (T_SLOTS * J_DIM) / 4; i += 256) d2[i] = s2[i];
        if (tid < J_DIM / 4)
            ((float4*)sUs)[tid] = ((const float4*)(g_us + b * J_DIM))[tid];
    }
    __syncthreads();

    #pragma unroll
    for (int uu = 0; uu < 2; uu++) {
        int u = tid + 256 * uu;
        int r = u >> 2, h = u & 3;
        int n = n0 + r;
        int hh = __ldg(hour + n);
        int msk[T_SLOTS];
        const int4* mp = (const int4*)(hmask + (size_t)n * T_SLOTS);
        #pragma unroll
        for (int i = 0; i < 6; i++) {
            int4 q = mp[i];
            msk[4*i] = q.x; msk[4*i+1] = q.y; msk[4*i+2] = q.z; msk[4*i+3] = q.w;
        }
        const float* usb = sUs + h * T_SLOTS;
        const float* tsb = sTs + hh * J_DIM + h * T_SLOTS;
        float sc[T_SLOTS];
        float mx = -3.0e38f;
        #pragma unroll
        for (int t = 0; t < T_SLOTS; t++) {
            sc[t] = msk[t] ? -1e9f : (usb[t] + tsb[t]);
            mx = fmaxf(mx, sc[t]);
        }
        float s = 0.0f;
        #pragma unroll
        for (int t = 0; t < T_SLOTS; t++) {
            float e = __expf(sc[t] - mx);
            sc[t] = e; s += e;
        }
        float inv = 1.0f / s;
        float* ar = sA + r * J_DIM + h * T_SLOTS;
        #pragma unroll
        for (int t = 0; t < T_SLOTS; t++) ar[t] = sc[t] * inv;
    }
    __syncthreads();

    // coalesced copy: 128*96 floats = 3072 float4
    const float4* s = (const float4*)sA;
    float4* d = (float4*)(g_att + (size_t)n0 * J_DIM);
    #pragma unroll
    for (int i = tid; i < 3072; i += 256) d[i] = s[i];
}

// ===========================================================================
// MAIN: pure GEMM. 2048 blocks = (1024 rowblocks x 2 colhalves), 256 thr,
// dyn smem ~73KB -> 2 blocks/SM. Warp w -> rows [8w,8w+8); lane l -> u64
// cols {2l, 2l+1} of this col-half (LDS.128). att: uniform LDS.32+pack_dup.
// Per SMSP/j @4 warps: 128 FMA2 = 256 cyc vs 192 L1 wf/SM -> FMA-bound.
// ===========================================================================
#define MSM_W   0                              // u64 sW[96*64] = 48KB (12288 f)
#define MSM_ATT 12288                          // float sAtt[64*96] = 24KB
#define MSM_F   (MSM_ATT + 64 * J_DIM)         // 18432 floats
#define MSM_B   (MSM_F * 4)                    // 73728 B

__global__ __launch_bounds__(256, 2) void main_kernel(
    const float* __restrict__ bu, float* __restrict__ out)
{
    extern __shared__ float msm[];
    u64*   sW   = (u64*)(msm + MSM_W);         // [j][64 u64 cols of half]
    float* sAtt = msm + MSM_ATT;               // [r][96]

    int tid = threadIdx.x;
    int bx  = blockIdx.x;
    int rb  = bx >> 1, ch = bx & 1;
    int n0  = rb * 64;

    // load W2 col-half: src f4 row j has 64; take [ch*32, ch*32+32)
    {
        const float4* src = (const float4*)g_W2;
        float4* dst = (float4*)sW;
        #pragma unroll
        for (int i = tid; i < J_DIM * 32; i += 256) {
            int j = i >> 5, q = i & 31;
            dst[i] = src[j * 64 + ch * 32 + q];
        }
    }
    // load att tile: 64 rows x 24 f4 = 1536 f4, contiguous
    {
        const float4* src = (const float4*)(g_att + (size_t)n0 * J_DIM);
        float4* dst = (float4*)sAtt;
        #pragma unroll
        for (int i = tid; i < 1536; i += 256) dst[i] = src[i];
    }
    __syncthreads();

    int w = tid >> 5, l = tid & 31;
    int r0 = w * 8;

    u64 acc[8][2];
    {
        // f32 cols: ch*128 + 4l .. +3
        float4 bv = __ldg((const float4*)bu + ch * 32 + l);
        u64 blo = pack2(bv.x, bv.y), bhi = pack2(bv.z, bv.w);
        #pragma unroll
        for (int rr = 0; rr < 8; rr++) { acc[rr][0] = blo; acc[rr][1] = bhi; }
    }
    const ulonglong2* wp = (const ulonglong2*)sW;   // 32 u128 per j
    const float* ap = sAtt + r0 * J_DIM;
    #pragma unroll 2
    for (int j = 0; j < J_DIM; j++) {
        ulonglong2 wv = wp[j * 32 + l];
        #pragma unroll
        for (int rr = 0; rr < 8; rr++) {
            u64 a = pack_dup(ap[rr * J_DIM + j]);
            fma2(acc[rr][0], a, wv.x);
            fma2(acc[rr][1], a, wv.y);
        }
    }
    #pragma unroll
    for (int rr = 0; rr < 8; rr++) {
        float2 lo = unpack2(acc[rr][0]);
        float2 hi = unpack2(acc[rr][1]);
        ((float4*)out)[(size_t)(n0 + r0 + rr) * 64 + ch * 32 + l] =
            make_float4(lo.x, lo.y, hi.x, hi.y);
    }
}

extern "C" void kernel_launch(void* const* d_in, const int* in_sizes, int n_in,
                              void* d_out, int out_size) {
    const float* ts_emb = (const float*)d_in[0];
    const int*   user   = (const int*)  d_in[1];
    const int*   hour   = (const int*)  d_in[2];
    const int*   hmask  = (const int*)  d_in[3];
    const float* upt    = (const float*)d_in[4];
    const float* Wq     = (const float*)d_in[5];
    const float* bq     = (const float*)d_in[6];
    const float* Wk     = (const float*)d_in[7];
    const float* bk     = (const float*)d_in[8];
    const float* Wv     = (const float*)d_in[9];
    const float* bv     = (const float*)d_in[10];
    const float* Wu     = (const float*)d_in[11];
    const float* bu     = (const float*)d_in[12];
    float* out = (float*)d_out;

    preA<<<72 + 256, 256>>>(ts_emb, Wk, bk, Wv, bv, Wq, bq, user, upt);
    preB<<<96 + 9 + 192, 256>>>(Wu);

    cudaFuncSetAttribute(att_kernel, cudaFuncAttributeMaxDynamicSharedMemorySize, ASM_B);
    att_kernel<<<B_BATCH, 256, ASM_B>>>(hour, hmask);

    cudaFuncSetAttribute(main_kernel, cudaFuncAttributeMaxDynamicSharedMemorySize, MSM_B);
    main_kernel<<<2048, 256, MSM_B>>>(bu, out);
}